// round 1
// baseline (speedup 1.0000x reference)
#include <cuda_runtime.h>
#include <cuda_bf16.h>
#include <math.h>

#define T_DIM 8192
#define OBS 512
#define HID 2048
#define NOBJ 8

#define NCHUNK 128
#define LC (T_DIM / NCHUNK)   // 64

// Scratch (device globals; no allocation allowed).
// g_buf[0]=x_state (later reused as y), g_buf[1]=B (later bx), g_buf[2]=C, g_buf[3]=delta_raw (later A_bar)
__device__ float g_buf[4][(size_t)T_DIM * HID];
__device__ float g_aggA[NCHUNK * HID];
__device__ float g_aggB[NCHUNK * HID];
__device__ float g_hinit[NCHUNK * HID];

// ---------------------------------------------------------------------------
// GEMM: G[z][t][h] = sum_k X[t][k] * W_z[h][k]   (both K-major, "NT" gemm)
// 128x128 tile, BK=16, 256 threads, 8x8 microtile.
// ---------------------------------------------------------------------------
#define BM 128
#define BN 128
#define BK 16

__global__ __launch_bounds__(256, 2)
void gemm4_kernel(const float* __restrict__ X,
                  const float* __restrict__ w0, const float* __restrict__ w1,
                  const float* __restrict__ w2, const float* __restrict__ w3)
{
    const int z = blockIdx.z;
    const float* __restrict__ W = (z == 0) ? w0 : (z == 1) ? w1 : (z == 2) ? w2 : w3;
    float* __restrict__ G = g_buf[z];

    __shared__ float As[BK][BM + 4];
    __shared__ float Bs[BK][BN + 4];

    const int tid = threadIdx.x;
    const int m0 = blockIdx.y * BM;
    const int n0 = blockIdx.x * BN;
    const int tx = tid & 15;   // n sub-tile
    const int ty = tid >> 4;   // m sub-tile

    float acc[8][8];
#pragma unroll
    for (int i = 0; i < 8; i++)
#pragma unroll
        for (int j = 0; j < 8; j++) acc[i][j] = 0.f;

    for (int k0 = 0; k0 < OBS; k0 += BK) {
        // Load tiles (each thread: 2 float4 from X, 2 from W), store transposed.
#pragma unroll
        for (int j = 0; j < 2; j++) {
            int i   = tid + 256 * j;       // 0..511
            int row = i >> 2;              // 0..127
            int kc  = (i & 3) << 2;        // 0,4,8,12
            float4 v = *(const float4*)(X + (size_t)(m0 + row) * OBS + k0 + kc);
            As[kc + 0][row] = v.x; As[kc + 1][row] = v.y;
            As[kc + 2][row] = v.z; As[kc + 3][row] = v.w;
            float4 w = *(const float4*)(W + (size_t)(n0 + row) * OBS + k0 + kc);
            Bs[kc + 0][row] = w.x; Bs[kc + 1][row] = w.y;
            Bs[kc + 2][row] = w.z; Bs[kc + 3][row] = w.w;
        }
        __syncthreads();

#pragma unroll
        for (int k = 0; k < BK; k++) {
            float a[8], b[8];
            *(float4*)&a[0] = *(const float4*)&As[k][ty * 8];
            *(float4*)&a[4] = *(const float4*)&As[k][ty * 8 + 4];
            *(float4*)&b[0] = *(const float4*)&Bs[k][tx * 8];
            *(float4*)&b[4] = *(const float4*)&Bs[k][tx * 8 + 4];
#pragma unroll
            for (int i = 0; i < 8; i++)
#pragma unroll
                for (int j = 0; j < 8; j++)
                    acc[i][j] += a[i] * b[j];
        }
        __syncthreads();
    }

    // Store 8x8 per thread as float4 pairs.
#pragma unroll
    for (int i = 0; i < 8; i++) {
        size_t base = (size_t)(m0 + ty * 8 + i) * HID + n0 + tx * 8;
        *(float4*)(G + base)     = make_float4(acc[i][0], acc[i][1], acc[i][2], acc[i][3]);
        *(float4*)(G + base + 4) = make_float4(acc[i][4], acc[i][5], acc[i][6], acc[i][7]);
    }
}

// ---------------------------------------------------------------------------
// Elementwise: A_bar = exp(sigmoid(delta_raw) * (-exp(A_log[h])))  -> g_buf[3]
//              bx    = B * x_state                                  -> g_buf[1]
// ---------------------------------------------------------------------------
__global__ void elementwise_kernel(const float* __restrict__ A_log)
{
    size_t idx = (size_t)blockIdx.x * blockDim.x + threadIdx.x;
    int h = (int)(idx & (HID - 1));
    float xs = g_buf[0][idx];
    float Bv = g_buf[1][idx];
    float dr = g_buf[3][idx];
    float delta = 1.f / (1.f + __expf(-dr));
    // use expf (not __expf) for exp to keep accuracy tight on the decay factor
    float A = -expf(A_log[h]);
    g_buf[3][idx] = expf(delta * A);
    g_buf[1][idx] = Bv * xs;
}

// ---------------------------------------------------------------------------
// Scan pass 1: per-chunk aggregates (A_prod, B_agg) per channel.
// ---------------------------------------------------------------------------
__global__ void scan_chunk_kernel()
{
    int h = blockIdx.x * blockDim.x + threadIdx.x;   // 0..HID-1
    int c = blockIdx.y;                              // 0..NCHUNK-1
    size_t base = (size_t)(c * LC) * HID + h;
    float ap = 1.f, bb = 0.f;
#pragma unroll 4
    for (int i = 0; i < LC; i++) {
        float a  = g_buf[3][base];
        float bx = g_buf[1][base];
        ap *= a;
        bb = a * bb + bx;
        base += HID;
    }
    g_aggA[c * HID + h] = ap;
    g_aggB[c * HID + h] = bb;
}

// ---------------------------------------------------------------------------
// Scan pass 2: sequential scan of NCHUNK aggregates per channel -> h_init.
// ---------------------------------------------------------------------------
__global__ void scan_agg_kernel()
{
    int h = blockIdx.x * blockDim.x + threadIdx.x;   // 0..HID-1
    float hs = 0.f;
#pragma unroll 4
    for (int c = 0; c < NCHUNK; c++) {
        g_hinit[c * HID + h] = hs;
        hs = g_aggA[c * HID + h] * hs + g_aggB[c * HID + h];
    }
}

// ---------------------------------------------------------------------------
// Scan pass 3: apply within chunk, y = C * h  -> g_buf[0]
// ---------------------------------------------------------------------------
__global__ void scan_apply_kernel()
{
    int h = blockIdx.x * blockDim.x + threadIdx.x;
    int c = blockIdx.y;
    size_t base = (size_t)(c * LC) * HID + h;
    float hs = g_hinit[c * HID + h];
#pragma unroll 4
    for (int i = 0; i < LC; i++) {
        float a  = g_buf[3][base];
        float bx = g_buf[1][base];
        hs = a * hs + bx;
        g_buf[0][base] = g_buf[2][base] * hs;
        base += HID;
    }
}

// ---------------------------------------------------------------------------
// Output: out[t][n] = sum_h y[t][h]*W_out[n][h] + b_out[n] + sum_o x[t][o]*W_skip[n][o]
// One warp per timestep.
// ---------------------------------------------------------------------------
__global__ void out_kernel(const float* __restrict__ x,
                           const float* __restrict__ W_out,
                           const float* __restrict__ b_out,
                           const float* __restrict__ W_skip,
                           float* __restrict__ out)
{
    int warp = threadIdx.x >> 5;
    int lane = threadIdx.x & 31;
    int t = blockIdx.x * (blockDim.x >> 5) + warp;
    if (t >= T_DIM) return;

    float acc[NOBJ];
#pragma unroll
    for (int n = 0; n < NOBJ; n++) acc[n] = 0.f;

    const float* yrow = g_buf[0] + (size_t)t * HID;
    for (int h = lane; h < HID; h += 32) {
        float yv = yrow[h];
#pragma unroll
        for (int n = 0; n < NOBJ; n++) acc[n] += yv * W_out[n * HID + h];
    }
    const float* xrow = x + (size_t)t * OBS;
    for (int o = lane; o < OBS; o += 32) {
        float xv = xrow[o];
#pragma unroll
        for (int n = 0; n < NOBJ; n++) acc[n] += xv * W_skip[n * OBS + o];
    }
#pragma unroll
    for (int n = 0; n < NOBJ; n++) {
#pragma unroll
        for (int off = 16; off > 0; off >>= 1)
            acc[n] += __shfl_down_sync(0xFFFFFFFFu, acc[n], off);
    }
    if (lane == 0) {
#pragma unroll
        for (int n = 0; n < NOBJ; n++)
            out[(size_t)t * NOBJ + n] = acc[n] + b_out[n];
    }
}

// ---------------------------------------------------------------------------
extern "C" void kernel_launch(void* const* d_in, const int* in_sizes, int n_in,
                              void* d_out, int out_size)
{
    const float* x       = (const float*)d_in[0];
    const float* W_in    = (const float*)d_in[1];
    const float* W_B     = (const float*)d_in[2];
    const float* W_C     = (const float*)d_in[3];
    const float* W_delta = (const float*)d_in[4];
    const float* A_log   = (const float*)d_in[5];
    const float* W_out   = (const float*)d_in[6];
    const float* b_out   = (const float*)d_in[7];
    const float* W_skip  = (const float*)d_in[8];
    float* out = (float*)d_out;

    // 1) 4 GEMMs -> g_buf[0..3]
    dim3 gg(HID / BN, T_DIM / BM, 4);
    gemm4_kernel<<<gg, 256>>>(x, W_in, W_B, W_C, W_delta);

    // 2) elementwise gating
    elementwise_kernel<<<(T_DIM * (size_t)HID) / 256, 256>>>(A_log);

    // 3) chunked scan
    scan_chunk_kernel<<<dim3(HID / 256, NCHUNK), 256>>>();
    scan_agg_kernel<<<HID / 256, 256>>>();
    scan_apply_kernel<<<dim3(HID / 256, NCHUNK), 256>>>();

    // 4) output projection
    out_kernel<<<T_DIM / 8, 256>>>(x, W_out, b_out, W_skip, out);
}

// round 3
// speedup vs baseline: 1.9351x; 1.9351x over previous
#include <cuda_runtime.h>
#include <cuda_bf16.h>
#include <math.h>
#include <stdint.h>

#define T_DIM 8192
#define OBS 512
#define HID 2048
#define NOBJ 8

#define NCHUNK 128
#define LC (T_DIM / NCHUNK)   // 64

// ---------------------------------------------------------------------------
// Scratch (device globals; no allocation allowed).
// g_buf[0]=x_state (later y), g_buf[1]=B (later bx), g_buf[2]=C, g_buf[3]=delta_raw (later A_bar)
__device__ float g_buf[4][(size_t)T_DIM * HID];
__device__ float g_aggA[NCHUNK * HID];
__device__ float g_aggB[NCHUNK * HID];
__device__ float g_hinit[NCHUNK * HID];
// bf16 hi/lo split operands
__device__ __nv_bfloat16 g_xhi[(size_t)T_DIM * OBS];
__device__ __nv_bfloat16 g_xlo[(size_t)T_DIM * OBS];
__device__ __nv_bfloat16 g_whi[4ull * HID * OBS];
__device__ __nv_bfloat16 g_wlo[4ull * HID * OBS];

// ---------------------------------------------------------------------------
__device__ __forceinline__ uint32_t smem_to_u32(const void* p) {
    uint32_t a;
    asm("{ .reg .u64 t; cvta.to.shared.u64 t, %1; cvt.u32.u64 %0, t; }" : "=r"(a) : "l"(p));
    return a;
}
__device__ __forceinline__ void cp16(uint32_t dst, const void* src) {
    asm volatile("cp.async.cg.shared.global [%0], [%1], 16;" :: "r"(dst), "l"(src));
}
__device__ __forceinline__ void cp_commit() { asm volatile("cp.async.commit_group;"); }
__device__ __forceinline__ void ldsm4(uint32_t* r, uint32_t addr) {
    asm volatile("ldmatrix.sync.aligned.m8n8.x4.shared.b16 {%0,%1,%2,%3}, [%4];"
                 : "=r"(r[0]), "=r"(r[1]), "=r"(r[2]), "=r"(r[3]) : "r"(addr));
}
__device__ __forceinline__ void mma16816(float* c, const uint32_t* a, uint32_t b0, uint32_t b1) {
    asm volatile(
        "mma.sync.aligned.m16n8k16.row.col.f32.bf16.bf16.f32 "
        "{%0,%1,%2,%3}, {%4,%5,%6,%7}, {%8,%9}, {%0,%1,%2,%3};"
        : "+f"(c[0]), "+f"(c[1]), "+f"(c[2]), "+f"(c[3])
        : "r"(a[0]), "r"(a[1]), "r"(a[2]), "r"(a[3]), "r"(b0), "r"(b1));
}

// ---------------------------------------------------------------------------
// fp32 -> bf16 hi/lo conversion
// ---------------------------------------------------------------------------
__global__ void convert_x_kernel(const float* __restrict__ x) {
    size_t i = (size_t)blockIdx.x * blockDim.x + threadIdx.x;
    float v = x[i];
    __nv_bfloat16 h = __float2bfloat16(v);
    g_xhi[i] = h;
    g_xlo[i] = __float2bfloat16(v - __bfloat162float(h));
}
__global__ void convert_w_kernel(const float* __restrict__ w0, const float* __restrict__ w1,
                                 const float* __restrict__ w2, const float* __restrict__ w3) {
    int z = blockIdx.y;
    const float* __restrict__ W = (z == 0) ? w0 : (z == 1) ? w1 : (z == 2) ? w2 : w3;
    size_t i = (size_t)blockIdx.x * blockDim.x + threadIdx.x;
    float v = W[i];
    __nv_bfloat16 h = __float2bfloat16(v);
    size_t o = (size_t)z * HID * OBS + i;
    g_whi[o] = h;
    g_wlo[o] = __float2bfloat16(v - __bfloat162float(h));
}

// ---------------------------------------------------------------------------
// HMMA GEMM: G[z][t][h] = X[t,:] . W_z[h,:]  via bf16 hi/lo 3-MMA split.
// BM=128 (T), BN=128 (HID), BK=32 bf16. 8 warps, warp tile 64x32.
// 3-stage cp.async pipeline. smem rows padded to 80B (ldmatrix conflict-free).
// ---------------------------------------------------------------------------
#define GBM 128
#define GBN 128
#define GBK 32
#define NS (OBS / GBK)          // 16
#define ROWB 80                  // padded row bytes (32 bf16 = 64B data + 16B pad)
#define A_BYTES (GBM * ROWB)     // 10240
#define B_BYTES (GBN * ROWB)     // 10240
#define STAGE_BYTES (2 * A_BYTES + 2 * B_BYTES)   // 40960
#define NSTAGE 3
#define GEMM_SMEM (NSTAGE * STAGE_BYTES)          // 122880

__global__ __launch_bounds__(256, 1)
void gemm_hmma_kernel() {
    extern __shared__ char smem[];
    const uint32_t sbase = smem_to_u32(smem);
    const int tid = threadIdx.x;
    const int wid = tid >> 5;
    const int lane = tid & 31;
    const int wm = wid >> 2;         // 0..1 -> m offset *64
    const int wn = wid & 3;          // 0..3 -> n offset *32

    const int z = blockIdx.z;
    const int n0 = blockIdx.x * GBN;
    const int m0 = blockIdx.y * GBM;
    const __nv_bfloat16* __restrict__ whi = g_whi + (size_t)z * HID * OBS;
    const __nv_bfloat16* __restrict__ wlo = g_wlo + (size_t)z * HID * OBS;
    float* __restrict__ G = g_buf[z];

    float acc[4][4][4];   // [mi][ni][frag]
#pragma unroll
    for (int i = 0; i < 4; i++)
#pragma unroll
        for (int j = 0; j < 4; j++)
#pragma unroll
            for (int k = 0; k < 4; k++) acc[i][j][k] = 0.f;

    // load indices for this thread (A: 512 16B chunks, B: 512 chunks per buf)
    const int arow0 = tid >> 1;              // with i*128: rows 0..127, 2 chunks each? see below
    // Simpler mapping: idx = tid + 256*i over 512 -> row = idx>>2, c = idx&3
    auto load_stage = [&](int s, int bi) {
        const int k0 = s * GBK;
        const uint32_t st = sbase + bi * STAGE_BYTES;
#pragma unroll
        for (int i = 0; i < 2; i++) {
            int idx = tid + 256 * i;         // 0..511
            int row = idx >> 2, c = idx & 3;
            size_t gsrc = (size_t)(m0 + row) * OBS + k0 + c * 8;
            uint32_t dst = st + row * ROWB + c * 16;
            cp16(dst,            g_xhi + gsrc);
            cp16(dst + A_BYTES,  g_xlo + gsrc);
        }
#pragma unroll
        for (int i = 0; i < 2; i++) {
            int idx = tid + 256 * i;
            int row = idx >> 2, c = idx & 3;
            size_t gsrc = (size_t)(n0 + row) * OBS + k0 + c * 8;
            uint32_t dst = st + 2 * A_BYTES + row * ROWB + c * 16;
            cp16(dst,            whi + gsrc);
            cp16(dst + B_BYTES,  wlo + gsrc);
        }
        cp_commit();
    };

    load_stage(0, 0);
    load_stage(1, 1);

    for (int s = 0; s < NS; s++) {
        if (s + 1 < NS) asm volatile("cp.async.wait_group 1;" ::: "memory");
        else            asm volatile("cp.async.wait_group 0;" ::: "memory");
        __syncthreads();

        const int bi = s % NSTAGE;
        const uint32_t ab = sbase + bi * STAGE_BYTES;          // A hi
        const uint32_t bb = ab + 2 * A_BYTES;                  // B hi

#pragma unroll
        for (int ks = 0; ks < 2; ks++) {
            uint32_t ahi[4][4], alo[4][4];
#pragma unroll
            for (int mi = 0; mi < 4; mi++) {
                uint32_t addr = ab + (wm * 64 + mi * 16 + (lane & 15)) * ROWB
                              + ks * 32 + (lane >> 4) * 16;
                ldsm4(ahi[mi], addr);
                ldsm4(alo[mi], addr + A_BYTES);
            }
            uint32_t bhi[2][4], blo[2][4];
#pragma unroll
            for (int np = 0; np < 2; np++) {
                uint32_t addr = bb + (wn * 32 + np * 16 + (lane >> 4) * 8 + (lane & 7)) * ROWB
                              + ks * 32 + ((lane >> 3) & 1) * 16;
                ldsm4(bhi[np], addr);
                ldsm4(blo[np], addr + B_BYTES);
            }
#pragma unroll
            for (int mi = 0; mi < 4; mi++) {
#pragma unroll
                for (int ni = 0; ni < 4; ni++) {
                    uint32_t h0 = bhi[ni >> 1][(ni & 1) * 2];
                    uint32_t h1 = bhi[ni >> 1][(ni & 1) * 2 + 1];
                    uint32_t l0 = blo[ni >> 1][(ni & 1) * 2];
                    uint32_t l1 = blo[ni >> 1][(ni & 1) * 2 + 1];
                    mma16816(acc[mi][ni], ahi[mi], h0, h1);
                    mma16816(acc[mi][ni], ahi[mi], l0, l1);
                    mma16816(acc[mi][ni], alo[mi], h0, h1);
                }
            }
        }
        __syncthreads();
        if (s + 2 < NS) load_stage(s + 2, (s + 2) % NSTAGE);
    }

    // Epilogue: direct store
#pragma unroll
    for (int mi = 0; mi < 4; mi++) {
        int row = m0 + wm * 64 + mi * 16 + (lane >> 2);
#pragma unroll
        for (int ni = 0; ni < 4; ni++) {
            int col = n0 + wn * 32 + ni * 8 + (lane & 3) * 2;
            *(float2*)(G + (size_t)row * HID + col) =
                make_float2(acc[mi][ni][0], acc[mi][ni][1]);
            *(float2*)(G + (size_t)(row + 8) * HID + col) =
                make_float2(acc[mi][ni][2], acc[mi][ni][3]);
        }
    }
}

// ---------------------------------------------------------------------------
// Scan pass 1 (fused gating): a = exp(sigmoid(dr) * (-exp(A_log[h]))); bx = B*x_state
// ---------------------------------------------------------------------------
__global__ void scan_chunk_kernel(const float* __restrict__ A_log) {
    int h = blockIdx.x * blockDim.x + threadIdx.x;
    int c = blockIdx.y;
    float A = -expf(A_log[h]);
    size_t base = (size_t)(c * LC) * HID + h;
    float ap = 1.f, bb = 0.f;
#pragma unroll 4
    for (int i = 0; i < LC; i++) {
        float xs = g_buf[0][base];
        float Bv = g_buf[1][base];
        float dr = g_buf[3][base];
        float delta = 1.f / (1.f + __expf(-dr));
        float a = expf(delta * A);
        float bx = Bv * xs;
        g_buf[3][base] = a;
        g_buf[1][base] = bx;
        ap *= a;
        bb = a * bb + bx;
        base += HID;
    }
    g_aggA[c * HID + h] = ap;
    g_aggB[c * HID + h] = bb;
}

// ---------------------------------------------------------------------------
// Scan pass 2: warp-parallel scan of NCHUNK aggregates per channel.
// ---------------------------------------------------------------------------
__global__ void scan_agg_kernel() {
    int warp = threadIdx.x >> 5;
    int lane = threadIdx.x & 31;
    int h = blockIdx.x * 8 + warp;

    float a_loc[4], b_loc[4];
    float ca = 1.f, cb = 0.f;
    int cbase = lane * 4;
#pragma unroll
    for (int j = 0; j < 4; j++) {
        float a = g_aggA[(cbase + j) * HID + h];
        float b = g_aggB[(cbase + j) * HID + h];
        a_loc[j] = a; b_loc[j] = b;
        cb = a * cb + b;
        ca *= a;
    }
    float ia = ca, ib = cb;
#pragma unroll
    for (int off = 1; off < 32; off <<= 1) {
        float pa = __shfl_up_sync(0xFFFFFFFFu, ia, off);
        float pb = __shfl_up_sync(0xFFFFFFFFu, ib, off);
        if (lane >= off) {
            ib = ia * pb + ib;
            ia = ia * pa;
        }
    }
    float eb = __shfl_up_sync(0xFFFFFFFFu, ib, 1);
    if (lane == 0) eb = 0.f;
    float hcur = eb;
#pragma unroll
    for (int j = 0; j < 4; j++) {
        g_hinit[(cbase + j) * HID + h] = hcur;
        hcur = a_loc[j] * hcur + b_loc[j];
    }
}

// ---------------------------------------------------------------------------
// Scan pass 3: apply within chunk, y = C * h  -> g_buf[0]
// ---------------------------------------------------------------------------
__global__ void scan_apply_kernel() {
    int h = blockIdx.x * blockDim.x + threadIdx.x;
    int c = blockIdx.y;
    size_t base = (size_t)(c * LC) * HID + h;
    float hs = g_hinit[c * HID + h];
#pragma unroll 4
    for (int i = 0; i < LC; i++) {
        float a = g_buf[3][base];
        float bx = g_buf[1][base];
        hs = a * hs + bx;
        g_buf[0][base] = g_buf[2][base] * hs;
        base += HID;
    }
}

// ---------------------------------------------------------------------------
// Output projection: warp per timestep.
// ---------------------------------------------------------------------------
__global__ void out_kernel(const float* __restrict__ x,
                           const float* __restrict__ W_out,
                           const float* __restrict__ b_out,
                           const float* __restrict__ W_skip,
                           float* __restrict__ out) {
    int warp = threadIdx.x >> 5;
    int lane = threadIdx.x & 31;
    int t = blockIdx.x * (blockDim.x >> 5) + warp;
    if (t >= T_DIM) return;

    float acc[NOBJ];
#pragma unroll
    for (int n = 0; n < NOBJ; n++) acc[n] = 0.f;

    const float* yrow = g_buf[0] + (size_t)t * HID;
    for (int h = lane; h < HID; h += 32) {
        float yv = yrow[h];
#pragma unroll
        for (int n = 0; n < NOBJ; n++) acc[n] += yv * W_out[n * HID + h];
    }
    const float* xrow = x + (size_t)t * OBS;
    for (int o = lane; o < OBS; o += 32) {
        float xv = xrow[o];
#pragma unroll
        for (int n = 0; n < NOBJ; n++) acc[n] += xv * W_skip[n * OBS + o];
    }
#pragma unroll
    for (int n = 0; n < NOBJ; n++) {
#pragma unroll
        for (int off = 16; off > 0; off >>= 1)
            acc[n] += __shfl_down_sync(0xFFFFFFFFu, acc[n], off);
    }
    if (lane == 0) {
#pragma unroll
        for (int n = 0; n < NOBJ; n++)
            out[(size_t)t * NOBJ + n] = acc[n] + b_out[n];
    }
}

// ---------------------------------------------------------------------------
extern "C" void kernel_launch(void* const* d_in, const int* in_sizes, int n_in,
                              void* d_out, int out_size) {
    const float* x       = (const float*)d_in[0];
    const float* W_in    = (const float*)d_in[1];
    const float* W_B     = (const float*)d_in[2];
    const float* W_C     = (const float*)d_in[3];
    const float* W_delta = (const float*)d_in[4];
    const float* A_log   = (const float*)d_in[5];
    const float* W_out   = (const float*)d_in[6];
    const float* b_out   = (const float*)d_in[7];
    const float* W_skip  = (const float*)d_in[8];
    float* out = (float*)d_out;

    cudaFuncSetAttribute(gemm_hmma_kernel, cudaFuncAttributeMaxDynamicSharedMemorySize, GEMM_SMEM);

    // 0) bf16 hi/lo split of X and the four weight matrices
    convert_x_kernel<<<(T_DIM * OBS) / 256, 256>>>(x);
    convert_w_kernel<<<dim3((HID * OBS) / 256, 4), 256>>>(W_in, W_B, W_C, W_delta);

    // 1) 4 GEMMs on tensor cores -> g_buf[0..3]
    gemm_hmma_kernel<<<dim3(HID / GBN, T_DIM / GBM, 4), 256, GEMM_SMEM>>>();

    // 2+3) fused gating + chunked scan
    scan_chunk_kernel<<<dim3(HID / 256, NCHUNK), 256>>>(A_log);
    scan_agg_kernel<<<HID / 8, 256>>>();
    scan_apply_kernel<<<dim3(HID / 256, NCHUNK), 256>>>();

    // 4) output projection
    out_kernel<<<T_DIM / 8, 256>>>(x, W_out, b_out, W_skip, out);
}

// round 4
// speedup vs baseline: 2.1030x; 1.0868x over previous
#include <cuda_runtime.h>
#include <cuda_bf16.h>
#include <math.h>
#include <stdint.h>

#define T_DIM 8192
#define OBS 512
#define HID 2048
#define NOBJ 8

#define NCHUNK 128
#define LC (T_DIM / NCHUNK)   // 64

// ---------------------------------------------------------------------------
// Scratch (device globals; no allocation allowed).
// g_buf[0]=x_state (later y), g_buf[1]=B (later bx), g_buf[2]=C, g_buf[3]=delta_raw (later A_bar)
__device__ float g_buf[4][(size_t)T_DIM * HID];
__device__ float g_aggA[NCHUNK * HID];
__device__ float g_aggB[NCHUNK * HID];
__device__ float g_hinit[NCHUNK * HID];
// bf16 hi/lo split operands
__device__ __nv_bfloat16 g_xhi[(size_t)T_DIM * OBS];
__device__ __nv_bfloat16 g_xlo[(size_t)T_DIM * OBS];
__device__ __nv_bfloat16 g_whi[4ull * HID * OBS];
__device__ __nv_bfloat16 g_wlo[4ull * HID * OBS];

// ---------------------------------------------------------------------------
__device__ __forceinline__ uint32_t smem_to_u32(const void* p) {
    uint32_t a;
    asm("{ .reg .u64 t; cvta.to.shared.u64 t, %1; cvt.u32.u64 %0, t; }" : "=r"(a) : "l"(p));
    return a;
}
__device__ __forceinline__ void cp16(uint32_t dst, const void* src) {
    asm volatile("cp.async.cg.shared.global [%0], [%1], 16;" :: "r"(dst), "l"(src));
}
__device__ __forceinline__ void cp_commit() { asm volatile("cp.async.commit_group;"); }
__device__ __forceinline__ void ldsm4(uint32_t* r, uint32_t addr) {
    asm volatile("ldmatrix.sync.aligned.m8n8.x4.shared.b16 {%0,%1,%2,%3}, [%4];"
                 : "=r"(r[0]), "=r"(r[1]), "=r"(r[2]), "=r"(r[3]) : "r"(addr));
}
__device__ __forceinline__ void mma16816(float* c, const uint32_t* a, uint32_t b0, uint32_t b1) {
    asm volatile(
        "mma.sync.aligned.m16n8k16.row.col.f32.bf16.bf16.f32 "
        "{%0,%1,%2,%3}, {%4,%5,%6,%7}, {%8,%9}, {%0,%1,%2,%3};"
        : "+f"(c[0]), "+f"(c[1]), "+f"(c[2]), "+f"(c[3])
        : "r"(a[0]), "r"(a[1]), "r"(a[2]), "r"(a[3]), "r"(b0), "r"(b1));
}

// ---------------------------------------------------------------------------
// fp32 -> bf16 hi/lo conversion (vectorized)
// ---------------------------------------------------------------------------
__global__ void convert_x_kernel(const float* __restrict__ x) {
    size_t i = ((size_t)blockIdx.x * blockDim.x + threadIdx.x) * 4;
    float4 v = *(const float4*)(x + i);
    __nv_bfloat16 h0 = __float2bfloat16(v.x), h1 = __float2bfloat16(v.y);
    __nv_bfloat16 h2 = __float2bfloat16(v.z), h3 = __float2bfloat16(v.w);
    *(uint2*)(g_xhi + i) = *(uint2*)&(__nv_bfloat16[4]){h0, h1, h2, h3};
    __nv_bfloat16 l0 = __float2bfloat16(v.x - __bfloat162float(h0));
    __nv_bfloat16 l1 = __float2bfloat16(v.y - __bfloat162float(h1));
    __nv_bfloat16 l2 = __float2bfloat16(v.z - __bfloat162float(h2));
    __nv_bfloat16 l3 = __float2bfloat16(v.w - __bfloat162float(h3));
    *(uint2*)(g_xlo + i) = *(uint2*)&(__nv_bfloat16[4]){l0, l1, l2, l3};
}
__global__ void convert_w_kernel(const float* __restrict__ w0, const float* __restrict__ w1,
                                 const float* __restrict__ w2, const float* __restrict__ w3) {
    int z = blockIdx.y;
    const float* __restrict__ W = (z == 0) ? w0 : (z == 1) ? w1 : (z == 2) ? w2 : w3;
    size_t i = ((size_t)blockIdx.x * blockDim.x + threadIdx.x) * 4;
    float4 v = *(const float4*)(W + i);
    size_t o = (size_t)z * HID * OBS + i;
    __nv_bfloat16 h0 = __float2bfloat16(v.x), h1 = __float2bfloat16(v.y);
    __nv_bfloat16 h2 = __float2bfloat16(v.z), h3 = __float2bfloat16(v.w);
    *(uint2*)(g_whi + o) = *(uint2*)&(__nv_bfloat16[4]){h0, h1, h2, h3};
    __nv_bfloat16 l0 = __float2bfloat16(v.x - __bfloat162float(h0));
    __nv_bfloat16 l1 = __float2bfloat16(v.y - __bfloat162float(h1));
    __nv_bfloat16 l2 = __float2bfloat16(v.z - __bfloat162float(h2));
    __nv_bfloat16 l3 = __float2bfloat16(v.w - __bfloat162float(h3));
    *(uint2*)(g_wlo + o) = *(uint2*)&(__nv_bfloat16[4]){l0, l1, l2, l3};
}

// ---------------------------------------------------------------------------
// HMMA GEMM: G[z][t][h] = X[t,:] . W_z[h,:]  via bf16 hi/lo 3-MMA split.
// BM=256 (T), BN=128 (HID), BK=32 bf16. 8 warps as 4x2, warp tile 64x64.
// Double-buffered cp.async. smem rows padded to 80B (ldmatrix conflict-free).
// ---------------------------------------------------------------------------
#define GBM 256
#define GBN 128
#define GBK 32
#define NS (OBS / GBK)           // 16
#define ROWB 80
#define A_BYTES (GBM * ROWB)     // 20480
#define B_BYTES (GBN * ROWB)     // 10240
#define STAGE_BYTES (2 * A_BYTES + 2 * B_BYTES)   // 61440
#define GEMM_SMEM (2 * STAGE_BYTES)               // 122880

__global__ __launch_bounds__(256, 1)
void gemm_hmma_kernel() {
    extern __shared__ char smem[];
    const uint32_t sbase = smem_to_u32(smem);
    const int tid = threadIdx.x;
    const int wid = tid >> 5;
    const int lane = tid & 31;
    const int wm = wid >> 1;         // 0..3 -> m offset *64
    const int wn = wid & 1;          // 0..1 -> n offset *64

    const int z = blockIdx.z;
    const int n0 = blockIdx.x * GBN;
    const int m0 = blockIdx.y * GBM;
    const __nv_bfloat16* __restrict__ whi = g_whi + (size_t)z * HID * OBS;
    const __nv_bfloat16* __restrict__ wlo = g_wlo + (size_t)z * HID * OBS;
    float* __restrict__ G = g_buf[z];

    float acc[4][8][4];   // [mi][n8-frag][frag]
#pragma unroll
    for (int i = 0; i < 4; i++)
#pragma unroll
        for (int j = 0; j < 8; j++)
#pragma unroll
            for (int k = 0; k < 4; k++) acc[i][j][k] = 0.f;

    auto load_stage = [&](int s, int bi) {
        const int k0 = s * GBK;
        const uint32_t st = sbase + bi * STAGE_BYTES;
        // A: 256 rows x 4 chunks (hi & lo)
#pragma unroll
        for (int i = 0; i < 4; i++) {
            int idx = tid + 256 * i;          // 0..1023
            int row = idx >> 2, c = idx & 3;
            size_t gsrc = (size_t)(m0 + row) * OBS + k0 + c * 8;
            uint32_t dst = st + row * ROWB + c * 16;
            cp16(dst,           g_xhi + gsrc);
            cp16(dst + A_BYTES, g_xlo + gsrc);
        }
        // B: 128 rows x 4 chunks (hi & lo)
#pragma unroll
        for (int i = 0; i < 2; i++) {
            int idx = tid + 256 * i;          // 0..511
            int row = idx >> 2, c = idx & 3;
            size_t gsrc = (size_t)(n0 + row) * OBS + k0 + c * 8;
            uint32_t dst = st + 2 * A_BYTES + row * ROWB + c * 16;
            cp16(dst,           whi + gsrc);
            cp16(dst + B_BYTES, wlo + gsrc);
        }
        cp_commit();
    };

    load_stage(0, 0);

    for (int s = 0; s < NS; s++) {
        if (s + 1 < NS) {
            load_stage(s + 1, (s + 1) & 1);
            asm volatile("cp.async.wait_group 1;" ::: "memory");
        } else {
            asm volatile("cp.async.wait_group 0;" ::: "memory");
        }
        __syncthreads();

        const uint32_t ab = sbase + (s & 1) * STAGE_BYTES;   // A hi
        const uint32_t bb = ab + 2 * A_BYTES;                // B hi

#pragma unroll
        for (int ks = 0; ks < 2; ks++) {
            uint32_t ahi[4][4], alo[4][4];
#pragma unroll
            for (int mi = 0; mi < 4; mi++) {
                uint32_t addr = ab + (wm * 64 + mi * 16 + (lane & 15)) * ROWB
                              + ks * 32 + (lane >> 4) * 16;
                ldsm4(ahi[mi], addr);
                ldsm4(alo[mi], addr + A_BYTES);
            }
            uint32_t bhi[4][4], blo[4][4];
#pragma unroll
            for (int np = 0; np < 4; np++) {
                uint32_t addr = bb + (wn * 64 + np * 16 + (lane >> 4) * 8 + (lane & 7)) * ROWB
                              + ks * 32 + ((lane >> 3) & 1) * 16;
                ldsm4(bhi[np], addr);
                ldsm4(blo[np], addr + B_BYTES);
            }
            // term-major: hh, hl, lh — consecutive MMAs hit different accumulators
#pragma unroll
            for (int mi = 0; mi < 4; mi++)
#pragma unroll
                for (int np = 0; np < 4; np++) {
                    mma16816(acc[mi][np * 2],     ahi[mi], bhi[np][0], bhi[np][1]);
                    mma16816(acc[mi][np * 2 + 1], ahi[mi], bhi[np][2], bhi[np][3]);
                }
#pragma unroll
            for (int mi = 0; mi < 4; mi++)
#pragma unroll
                for (int np = 0; np < 4; np++) {
                    mma16816(acc[mi][np * 2],     ahi[mi], blo[np][0], blo[np][1]);
                    mma16816(acc[mi][np * 2 + 1], ahi[mi], blo[np][2], blo[np][3]);
                }
#pragma unroll
            for (int mi = 0; mi < 4; mi++)
#pragma unroll
                for (int np = 0; np < 4; np++) {
                    mma16816(acc[mi][np * 2],     alo[mi], bhi[np][0], bhi[np][1]);
                    mma16816(acc[mi][np * 2 + 1], alo[mi], bhi[np][2], bhi[np][3]);
                }
        }
        __syncthreads();
    }

    // Epilogue: direct store
#pragma unroll
    for (int mi = 0; mi < 4; mi++) {
        int row = m0 + wm * 64 + mi * 16 + (lane >> 2);
#pragma unroll
        for (int ni = 0; ni < 8; ni++) {
            int col = n0 + wn * 64 + ni * 8 + (lane & 3) * 2;
            *(float2*)(G + (size_t)row * HID + col) =
                make_float2(acc[mi][ni][0], acc[mi][ni][1]);
            *(float2*)(G + (size_t)(row + 8) * HID + col) =
                make_float2(acc[mi][ni][2], acc[mi][ni][3]);
        }
    }
}

// ---------------------------------------------------------------------------
// Scan pass 1 (fused gating): a = exp(sigmoid(dr) * (-exp(A_log[h]))); bx = B*x_state
// ---------------------------------------------------------------------------
__global__ void scan_chunk_kernel(const float* __restrict__ A_log) {
    int h = blockIdx.x * blockDim.x + threadIdx.x;
    int c = blockIdx.y;
    float A = -expf(A_log[h]);
    size_t base = (size_t)(c * LC) * HID + h;
    float ap = 1.f, bb = 0.f;
#pragma unroll 4
    for (int i = 0; i < LC; i++) {
        float xs = g_buf[0][base];
        float Bv = g_buf[1][base];
        float dr = g_buf[3][base];
        float delta = 1.f / (1.f + __expf(-dr));
        float a = expf(delta * A);
        float bx = Bv * xs;
        g_buf[3][base] = a;
        g_buf[1][base] = bx;
        ap *= a;
        bb = a * bb + bx;
        base += HID;
    }
    g_aggA[c * HID + h] = ap;
    g_aggB[c * HID + h] = bb;
}

// ---------------------------------------------------------------------------
// Scan pass 2: warp-parallel scan of NCHUNK aggregates per channel.
// ---------------------------------------------------------------------------
__global__ void scan_agg_kernel() {
    int warp = threadIdx.x >> 5;
    int lane = threadIdx.x & 31;
    int h = blockIdx.x * 8 + warp;

    float a_loc[4], b_loc[4];
    float ca = 1.f, cb = 0.f;
    int cbase = lane * 4;
#pragma unroll
    for (int j = 0; j < 4; j++) {
        float a = g_aggA[(cbase + j) * HID + h];
        float b = g_aggB[(cbase + j) * HID + h];
        a_loc[j] = a; b_loc[j] = b;
        cb = a * cb + b;
        ca *= a;
    }
    float ia = ca, ib = cb;
#pragma unroll
    for (int off = 1; off < 32; off <<= 1) {
        float pa = __shfl_up_sync(0xFFFFFFFFu, ia, off);
        float pb = __shfl_up_sync(0xFFFFFFFFu, ib, off);
        if (lane >= off) {
            ib = ia * pb + ib;
            ia = ia * pa;
        }
    }
    float eb = __shfl_up_sync(0xFFFFFFFFu, ib, 1);
    if (lane == 0) eb = 0.f;
    float hcur = eb;
#pragma unroll
    for (int j = 0; j < 4; j++) {
        g_hinit[(cbase + j) * HID + h] = hcur;
        hcur = a_loc[j] * hcur + b_loc[j];
    }
}

// ---------------------------------------------------------------------------
// Scan pass 3: apply within chunk, y = C * h  -> g_buf[0]
// ---------------------------------------------------------------------------
__global__ void scan_apply_kernel() {
    int h = blockIdx.x * blockDim.x + threadIdx.x;
    int c = blockIdx.y;
    size_t base = (size_t)(c * LC) * HID + h;
    float hs = g_hinit[c * HID + h];
#pragma unroll 4
    for (int i = 0; i < LC; i++) {
        float a = g_buf[3][base];
        float bx = g_buf[1][base];
        hs = a * hs + bx;
        g_buf[0][base] = g_buf[2][base] * hs;
        base += HID;
    }
}

// ---------------------------------------------------------------------------
// Output projection: warp per timestep.
// ---------------------------------------------------------------------------
__global__ void out_kernel(const float* __restrict__ x,
                           const float* __restrict__ W_out,
                           const float* __restrict__ b_out,
                           const float* __restrict__ W_skip,
                           float* __restrict__ out) {
    int warp = threadIdx.x >> 5;
    int lane = threadIdx.x & 31;
    int t = blockIdx.x * (blockDim.x >> 5) + warp;
    if (t >= T_DIM) return;

    float acc[NOBJ];
#pragma unroll
    for (int n = 0; n < NOBJ; n++) acc[n] = 0.f;

    const float* yrow = g_buf[0] + (size_t)t * HID;
    for (int h = lane; h < HID; h += 32) {
        float yv = yrow[h];
#pragma unroll
        for (int n = 0; n < NOBJ; n++) acc[n] += yv * W_out[n * HID + h];
    }
    const float* xrow = x + (size_t)t * OBS;
    for (int o = lane; o < OBS; o += 32) {
        float xv = xrow[o];
#pragma unroll
        for (int n = 0; n < NOBJ; n++) acc[n] += xv * W_skip[n * OBS + o];
    }
#pragma unroll
    for (int n = 0; n < NOBJ; n++) {
#pragma unroll
        for (int off = 16; off > 0; off >>= 1)
            acc[n] += __shfl_down_sync(0xFFFFFFFFu, acc[n], off);
    }
    if (lane == 0) {
#pragma unroll
        for (int n = 0; n < NOBJ; n++)
            out[(size_t)t * NOBJ + n] = acc[n] + b_out[n];
    }
}

// ---------------------------------------------------------------------------
extern "C" void kernel_launch(void* const* d_in, const int* in_sizes, int n_in,
                              void* d_out, int out_size) {
    const float* x       = (const float*)d_in[0];
    const float* W_in    = (const float*)d_in[1];
    const float* W_B     = (const float*)d_in[2];
    const float* W_C     = (const float*)d_in[3];
    const float* W_delta = (const float*)d_in[4];
    const float* A_log   = (const float*)d_in[5];
    const float* W_out   = (const float*)d_in[6];
    const float* b_out   = (const float*)d_in[7];
    const float* W_skip  = (const float*)d_in[8];
    float* out = (float*)d_out;

    cudaFuncSetAttribute(gemm_hmma_kernel, cudaFuncAttributeMaxDynamicSharedMemorySize, GEMM_SMEM);

    // 0) bf16 hi/lo split of X and the four weight matrices
    convert_x_kernel<<<(T_DIM * OBS) / 1024, 256>>>(x);
    convert_w_kernel<<<dim3((HID * OBS) / 1024, 4), 256>>>(W_in, W_B, W_C, W_delta);

    // 1) 4 GEMMs on tensor cores -> g_buf[0..3]
    gemm_hmma_kernel<<<dim3(HID / GBN, T_DIM / GBM, 4), 256, GEMM_SMEM>>>();

    // 2+3) fused gating + chunked scan
    scan_chunk_kernel<<<dim3(HID / 256, NCHUNK), 256>>>(A_log);
    scan_agg_kernel<<<HID / 8, 256>>>();
    scan_apply_kernel<<<dim3(HID / 256, NCHUNK), 256>>>();

    // 4) output projection
    out_kernel<<<T_DIM / 8, 256>>>(x, W_out, b_out, W_skip, out);
}

// round 5
// speedup vs baseline: 2.4581x; 1.1688x over previous
#include <cuda_runtime.h>
#include <cuda_bf16.h>
#include <math.h>
#include <stdint.h>

#define T_DIM 8192
#define OBS 512
#define HID 2048
#define NOBJ 8

#define NCHUNK 128
#define LC (T_DIM / NCHUNK)   // 64

// ---------------------------------------------------------------------------
// Scratch (device globals; no allocation allowed).
// g_buf[0]=x_state (later y), g_buf[1]=B (later bx), g_buf[2]=C, g_buf[3]=delta_raw (later A_bar)
__device__ float g_buf[4][(size_t)T_DIM * HID];
__device__ float g_aggA[NCHUNK * HID];
__device__ float g_aggB[NCHUNK * HID];
__device__ float g_hinit[NCHUNK * HID];
// bf16 hi/lo split operands
__device__ __nv_bfloat16 g_xhi[(size_t)T_DIM * OBS];
__device__ __nv_bfloat16 g_xlo[(size_t)T_DIM * OBS];
__device__ __nv_bfloat16 g_whi[4ull * HID * OBS];
__device__ __nv_bfloat16 g_wlo[4ull * HID * OBS];

// ---------------------------------------------------------------------------
__device__ __forceinline__ uint32_t smem_to_u32(const void* p) {
    uint32_t a;
    asm("{ .reg .u64 t; cvta.to.shared.u64 t, %1; cvt.u32.u64 %0, t; }" : "=r"(a) : "l"(p));
    return a;
}
__device__ __forceinline__ void cp16(uint32_t dst, const void* src) {
    asm volatile("cp.async.cg.shared.global [%0], [%1], 16;" :: "r"(dst), "l"(src));
}
__device__ __forceinline__ void cp_commit() { asm volatile("cp.async.commit_group;"); }
__device__ __forceinline__ void ldsm4(uint32_t* r, uint32_t addr) {
    asm volatile("ldmatrix.sync.aligned.m8n8.x4.shared.b16 {%0,%1,%2,%3}, [%4];"
                 : "=r"(r[0]), "=r"(r[1]), "=r"(r[2]), "=r"(r[3]) : "r"(addr));
}
__device__ __forceinline__ void mma16816(float* c, const uint32_t* a, uint32_t b0, uint32_t b1) {
    asm volatile(
        "mma.sync.aligned.m16n8k16.row.col.f32.bf16.bf16.f32 "
        "{%0,%1,%2,%3}, {%4,%5,%6,%7}, {%8,%9}, {%0,%1,%2,%3};"
        : "+f"(c[0]), "+f"(c[1]), "+f"(c[2]), "+f"(c[3])
        : "r"(a[0]), "r"(a[1]), "r"(a[2]), "r"(a[3]), "r"(b0), "r"(b1));
}
__device__ __forceinline__ uint32_t pack_bf16x2(float a, float b) {
    __nv_bfloat162 p = __floats2bfloat162_rn(a, b);
    return *(uint32_t*)&p;
}

// ---------------------------------------------------------------------------
// fp32 -> bf16 hi/lo conversion (vectorized)
// ---------------------------------------------------------------------------
__global__ void convert_x_kernel(const float* __restrict__ x) {
    size_t i = ((size_t)blockIdx.x * blockDim.x + threadIdx.x) * 4;
    float4 v = *(const float4*)(x + i);
    __nv_bfloat16 h0 = __float2bfloat16(v.x), h1 = __float2bfloat16(v.y);
    __nv_bfloat16 h2 = __float2bfloat16(v.z), h3 = __float2bfloat16(v.w);
    uint2 hp;
    hp.x = pack_bf16x2(__bfloat162float(h0), __bfloat162float(h1));
    hp.y = pack_bf16x2(__bfloat162float(h2), __bfloat162float(h3));
    *(uint2*)(g_xhi + i) = hp;
    uint2 lp;
    lp.x = pack_bf16x2(v.x - __bfloat162float(h0), v.y - __bfloat162float(h1));
    lp.y = pack_bf16x2(v.z - __bfloat162float(h2), v.w - __bfloat162float(h3));
    *(uint2*)(g_xlo + i) = lp;
}
__global__ void convert_w_kernel(const float* __restrict__ w0, const float* __restrict__ w1,
                                 const float* __restrict__ w2, const float* __restrict__ w3) {
    int z = blockIdx.y;
    const float* __restrict__ W = (z == 0) ? w0 : (z == 1) ? w1 : (z == 2) ? w2 : w3;
    size_t i = ((size_t)blockIdx.x * blockDim.x + threadIdx.x) * 4;
    float4 v = *(const float4*)(W + i);
    size_t o = (size_t)z * HID * OBS + i;
    __nv_bfloat16 h0 = __float2bfloat16(v.x), h1 = __float2bfloat16(v.y);
    __nv_bfloat16 h2 = __float2bfloat16(v.z), h3 = __float2bfloat16(v.w);
    uint2 hp;
    hp.x = pack_bf16x2(__bfloat162float(h0), __bfloat162float(h1));
    hp.y = pack_bf16x2(__bfloat162float(h2), __bfloat162float(h3));
    *(uint2*)(g_whi + o) = hp;
    uint2 lp;
    lp.x = pack_bf16x2(v.x - __bfloat162float(h0), v.y - __bfloat162float(h1));
    lp.y = pack_bf16x2(v.z - __bfloat162float(h2), v.w - __bfloat162float(h3));
    *(uint2*)(g_wlo + o) = lp;
}

// ---------------------------------------------------------------------------
// HMMA GEMM: G[z][t][h] = X[t,:] . W_z[h,:]  via bf16 hi/lo 3-MMA split.
// BM=128 (T), BN=128 (HID), BK=32 bf16. 4 warps as 2x2, warp tile 64x64.
// 128 threads, 2 CTAs/SM. Double-buffered cp.async. 80B padded rows.
// ---------------------------------------------------------------------------
#define GBM 128
#define GBN 128
#define GBK 32
#define NS (OBS / GBK)           // 16
#define ROWB 80
#define A_BYTES (GBM * ROWB)     // 10240
#define B_BYTES (GBN * ROWB)     // 10240
#define STAGE_BYTES (2 * A_BYTES + 2 * B_BYTES)   // 40960
#define GEMM_SMEM (2 * STAGE_BYTES)               // 81920

__global__ __launch_bounds__(128, 2)
void gemm_hmma_kernel() {
    extern __shared__ char smem[];
    const uint32_t sbase = smem_to_u32(smem);
    const int tid = threadIdx.x;
    const int wid = tid >> 5;
    const int lane = tid & 31;
    const int wm = wid >> 1;         // 0..1 -> m offset *64
    const int wn = wid & 1;          // 0..1 -> n offset *64

    const int z = blockIdx.z;
    const int n0 = blockIdx.x * GBN;
    const int m0 = blockIdx.y * GBM;
    const __nv_bfloat16* __restrict__ whi = g_whi + (size_t)z * HID * OBS;
    const __nv_bfloat16* __restrict__ wlo = g_wlo + (size_t)z * HID * OBS;
    float* __restrict__ G = g_buf[z];

    float acc[4][8][4];   // [mi][n8-frag][frag]
#pragma unroll
    for (int i = 0; i < 4; i++)
#pragma unroll
        for (int j = 0; j < 8; j++)
#pragma unroll
            for (int k = 0; k < 4; k++) acc[i][j][k] = 0.f;

    auto load_stage = [&](int s, int bi) {
        const int k0 = s * GBK;
        const uint32_t st = sbase + bi * STAGE_BYTES;
        // A: 128 rows x 4 chunks (hi & lo)
#pragma unroll
        for (int i = 0; i < 4; i++) {
            int idx = tid + 128 * i;          // 0..511
            int row = idx >> 2, c = idx & 3;
            size_t gsrc = (size_t)(m0 + row) * OBS + k0 + c * 8;
            uint32_t dst = st + row * ROWB + c * 16;
            cp16(dst,           g_xhi + gsrc);
            cp16(dst + A_BYTES, g_xlo + gsrc);
        }
        // B: 128 rows x 4 chunks (hi & lo)
#pragma unroll
        for (int i = 0; i < 4; i++) {
            int idx = tid + 128 * i;
            int row = idx >> 2, c = idx & 3;
            size_t gsrc = (size_t)(n0 + row) * OBS + k0 + c * 8;
            uint32_t dst = st + 2 * A_BYTES + row * ROWB + c * 16;
            cp16(dst,           whi + gsrc);
            cp16(dst + B_BYTES, wlo + gsrc);
        }
        cp_commit();
    };

    load_stage(0, 0);

    for (int s = 0; s < NS; s++) {
        if (s + 1 < NS) {
            load_stage(s + 1, (s + 1) & 1);
            asm volatile("cp.async.wait_group 1;" ::: "memory");
        } else {
            asm volatile("cp.async.wait_group 0;" ::: "memory");
        }
        __syncthreads();

        const uint32_t ab = sbase + (s & 1) * STAGE_BYTES;   // A hi
        const uint32_t bb = ab + 2 * A_BYTES;                // B hi

#pragma unroll
        for (int ks = 0; ks < 2; ks++) {
            uint32_t ahi[4][4], alo[4][4];
#pragma unroll
            for (int mi = 0; mi < 4; mi++) {
                uint32_t addr = ab + (wm * 64 + mi * 16 + (lane & 15)) * ROWB
                              + ks * 32 + (lane >> 4) * 16;
                ldsm4(ahi[mi], addr);
                ldsm4(alo[mi], addr + A_BYTES);
            }
            uint32_t bhi[4][4], blo[4][4];
#pragma unroll
            for (int np = 0; np < 4; np++) {
                uint32_t addr = bb + (wn * 64 + np * 16 + (lane >> 4) * 8 + (lane & 7)) * ROWB
                              + ks * 32 + ((lane >> 3) & 1) * 16;
                ldsm4(bhi[np], addr);
                ldsm4(blo[np], addr + B_BYTES);
            }
            // term-major: hh, hl, lh — consecutive MMAs hit different accumulators
#pragma unroll
            for (int mi = 0; mi < 4; mi++)
#pragma unroll
                for (int np = 0; np < 4; np++) {
                    mma16816(acc[mi][np * 2],     ahi[mi], bhi[np][0], bhi[np][1]);
                    mma16816(acc[mi][np * 2 + 1], ahi[mi], bhi[np][2], bhi[np][3]);
                }
#pragma unroll
            for (int mi = 0; mi < 4; mi++)
#pragma unroll
                for (int np = 0; np < 4; np++) {
                    mma16816(acc[mi][np * 2],     ahi[mi], blo[np][0], blo[np][1]);
                    mma16816(acc[mi][np * 2 + 1], ahi[mi], blo[np][2], blo[np][3]);
                }
#pragma unroll
            for (int mi = 0; mi < 4; mi++)
#pragma unroll
                for (int np = 0; np < 4; np++) {
                    mma16816(acc[mi][np * 2],     alo[mi], bhi[np][0], bhi[np][1]);
                    mma16816(acc[mi][np * 2 + 1], alo[mi], bhi[np][2], bhi[np][3]);
                }
        }
        __syncthreads();
    }

    // Epilogue: direct store
#pragma unroll
    for (int mi = 0; mi < 4; mi++) {
        int row = m0 + wm * 64 + mi * 16 + (lane >> 2);
#pragma unroll
        for (int ni = 0; ni < 8; ni++) {
            int col = n0 + wn * 64 + ni * 8 + (lane & 3) * 2;
            *(float2*)(G + (size_t)row * HID + col) =
                make_float2(acc[mi][ni][0], acc[mi][ni][1]);
            *(float2*)(G + (size_t)(row + 8) * HID + col) =
                make_float2(acc[mi][ni][2], acc[mi][ni][3]);
        }
    }
}

// ---------------------------------------------------------------------------
// Scan pass 1 (fused gating, 4 channels/thread, float4):
//   a = exp(sigmoid(dr) * (-exp(A_log[h]))); bx = B*x_state
// ---------------------------------------------------------------------------
__global__ void scan_chunk_kernel(const float* __restrict__ A_log) {
    int h = (blockIdx.x * blockDim.x + threadIdx.x) * 4;
    int c = blockIdx.y;
    float4 Al = *(const float4*)(A_log + h);
    float A0 = -expf(Al.x), A1 = -expf(Al.y), A2 = -expf(Al.z), A3 = -expf(Al.w);
    size_t base = (size_t)(c * LC) * HID + h;
    float4 ap = make_float4(1.f, 1.f, 1.f, 1.f);
    float4 bb = make_float4(0.f, 0.f, 0.f, 0.f);
#pragma unroll 2
    for (int i = 0; i < LC; i++) {
        float4 xs = *(const float4*)(g_buf[0] + base);
        float4 Bv = *(const float4*)(g_buf[1] + base);
        float4 dr = *(const float4*)(g_buf[3] + base);
        float4 a, bx;
        a.x = expf(A0 / (1.f + __expf(-dr.x)));
        a.y = expf(A1 / (1.f + __expf(-dr.y)));
        a.z = expf(A2 / (1.f + __expf(-dr.z)));
        a.w = expf(A3 / (1.f + __expf(-dr.w)));
        bx.x = Bv.x * xs.x; bx.y = Bv.y * xs.y; bx.z = Bv.z * xs.z; bx.w = Bv.w * xs.w;
        *(float4*)(g_buf[3] + base) = a;
        *(float4*)(g_buf[1] + base) = bx;
        ap.x *= a.x; ap.y *= a.y; ap.z *= a.z; ap.w *= a.w;
        bb.x = a.x * bb.x + bx.x; bb.y = a.y * bb.y + bx.y;
        bb.z = a.z * bb.z + bx.z; bb.w = a.w * bb.w + bx.w;
        base += HID;
    }
    *(float4*)(g_aggA + c * HID + h) = ap;
    *(float4*)(g_aggB + c * HID + h) = bb;
}

// ---------------------------------------------------------------------------
// Scan pass 2: warp-parallel scan of NCHUNK aggregates per channel.
// ---------------------------------------------------------------------------
__global__ void scan_agg_kernel() {
    int warp = threadIdx.x >> 5;
    int lane = threadIdx.x & 31;
    int h = blockIdx.x * 8 + warp;

    float a_loc[4], b_loc[4];
    float ca = 1.f, cb = 0.f;
    int cbase = lane * 4;
#pragma unroll
    for (int j = 0; j < 4; j++) {
        float a = g_aggA[(cbase + j) * HID + h];
        float b = g_aggB[(cbase + j) * HID + h];
        a_loc[j] = a; b_loc[j] = b;
        cb = a * cb + b;
        ca *= a;
    }
    float ia = ca, ib = cb;
#pragma unroll
    for (int off = 1; off < 32; off <<= 1) {
        float pa = __shfl_up_sync(0xFFFFFFFFu, ia, off);
        float pb = __shfl_up_sync(0xFFFFFFFFu, ib, off);
        if (lane >= off) {
            ib = ia * pb + ib;
            ia = ia * pa;
        }
    }
    float eb = __shfl_up_sync(0xFFFFFFFFu, ib, 1);
    if (lane == 0) eb = 0.f;
    float hcur = eb;
#pragma unroll
    for (int j = 0; j < 4; j++) {
        g_hinit[(cbase + j) * HID + h] = hcur;
        hcur = a_loc[j] * hcur + b_loc[j];
    }
}

// ---------------------------------------------------------------------------
// Scan pass 3: apply within chunk (4 channels/thread), y = C * h -> g_buf[0]
// ---------------------------------------------------------------------------
__global__ void scan_apply_kernel() {
    int h = (blockIdx.x * blockDim.x + threadIdx.x) * 4;
    int c = blockIdx.y;
    size_t base = (size_t)(c * LC) * HID + h;
    float4 hs = *(const float4*)(g_hinit + c * HID + h);
#pragma unroll 2
    for (int i = 0; i < LC; i++) {
        float4 a = *(const float4*)(g_buf[3] + base);
        float4 bx = *(const float4*)(g_buf[1] + base);
        float4 Cv = *(const float4*)(g_buf[2] + base);
        hs.x = a.x * hs.x + bx.x;
        hs.y = a.y * hs.y + bx.y;
        hs.z = a.z * hs.z + bx.z;
        hs.w = a.w * hs.w + bx.w;
        float4 y = make_float4(Cv.x * hs.x, Cv.y * hs.y, Cv.z * hs.z, Cv.w * hs.w);
        *(float4*)(g_buf[0] + base) = y;
        base += HID;
    }
}

// ---------------------------------------------------------------------------
// Output projection: warp per timestep.
// ---------------------------------------------------------------------------
__global__ void out_kernel(const float* __restrict__ x,
                           const float* __restrict__ W_out,
                           const float* __restrict__ b_out,
                           const float* __restrict__ W_skip,
                           float* __restrict__ out) {
    int warp = threadIdx.x >> 5;
    int lane = threadIdx.x & 31;
    int t = blockIdx.x * (blockDim.x >> 5) + warp;
    if (t >= T_DIM) return;

    float acc[NOBJ];
#pragma unroll
    for (int n = 0; n < NOBJ; n++) acc[n] = 0.f;

    const float* yrow = g_buf[0] + (size_t)t * HID;
    for (int h = lane; h < HID; h += 32) {
        float yv = yrow[h];
#pragma unroll
        for (int n = 0; n < NOBJ; n++) acc[n] += yv * W_out[n * HID + h];
    }
    const float* xrow = x + (size_t)t * OBS;
    for (int o = lane; o < OBS; o += 32) {
        float xv = xrow[o];
#pragma unroll
        for (int n = 0; n < NOBJ; n++) acc[n] += xv * W_skip[n * OBS + o];
    }
#pragma unroll
    for (int n = 0; n < NOBJ; n++) {
#pragma unroll
        for (int off = 16; off > 0; off >>= 1)
            acc[n] += __shfl_down_sync(0xFFFFFFFFu, acc[n], off);
    }
    if (lane == 0) {
#pragma unroll
        for (int n = 0; n < NOBJ; n++)
            out[(size_t)t * NOBJ + n] = acc[n] + b_out[n];
    }
}

// ---------------------------------------------------------------------------
extern "C" void kernel_launch(void* const* d_in, const int* in_sizes, int n_in,
                              void* d_out, int out_size) {
    const float* x       = (const float*)d_in[0];
    const float* W_in    = (const float*)d_in[1];
    const float* W_B     = (const float*)d_in[2];
    const float* W_C     = (const float*)d_in[3];
    const float* W_delta = (const float*)d_in[4];
    const float* A_log   = (const float*)d_in[5];
    const float* W_out   = (const float*)d_in[6];
    const float* b_out   = (const float*)d_in[7];
    const float* W_skip  = (const float*)d_in[8];
    float* out = (float*)d_out;

    cudaFuncSetAttribute(gemm_hmma_kernel, cudaFuncAttributeMaxDynamicSharedMemorySize, GEMM_SMEM);

    // 0) bf16 hi/lo split of X and the four weight matrices
    convert_x_kernel<<<(T_DIM * OBS) / 1024, 256>>>(x);
    convert_w_kernel<<<dim3((HID * OBS) / 1024, 4), 256>>>(W_in, W_B, W_C, W_delta);

    // 1) 4 GEMMs on tensor cores -> g_buf[0..3]
    gemm_hmma_kernel<<<dim3(HID / GBN, T_DIM / GBM, 4), 128, GEMM_SMEM>>>();

    // 2+3) fused gating + chunked scan
    scan_chunk_kernel<<<dim3(HID / 1024, NCHUNK), 256>>>(A_log);
    scan_agg_kernel<<<HID / 8, 256>>>();
    scan_apply_kernel<<<dim3(HID / 1024, NCHUNK), 256>>>();

    // 4) output projection
    out_kernel<<<T_DIM / 8, 256>>>(x, W_out, b_out, W_skip, out);
}